// round 10
// baseline (speedup 1.0000x reference)
#include <cuda_runtime.h>

// ---------------------------------------------------------------------------
// ChordProgressionLoss v10 — v9 math + perfect balance + software pipeline.
//   Every warp: EXACTLY 3 consecutive 58-row units (240 blocks x 24 warps
//   covers 17280 units >= 17242) -> no straggler warps (was 2-vs-3 units).
//   Pipelined: convert cur float4s->masks, prefetch next unit's 4 LDG.128,
//   then compute. Only the first load per warp is latency-exposed.
//   Masks via packed f32x2 magic-adds; jaccard bytes via PRMT; windows via
//   3 shuffles + dp4a; integer max; fixed-point sim. Exact -> deterministic.
// ---------------------------------------------------------------------------

#define THREADS 768
#define WPB 24
#define UPW 3

__device__ unsigned long long g_simSlots[32];
__device__ unsigned long long g_penSlots[32];
__device__ unsigned int       g_count = 0;

#define MAGIC2  0x4B4000004B400000ULL
#define INV12_2 0x3DAAAAAB3DAAAAABULL
#define BIAS2   0xBEEAAAABBEEAAAABULL

__device__ __forceinline__ unsigned pcmask(float4 v) {
    unsigned long long dxy, dzw, b1xy, b1zw, t, b2xy, b2zw;
    asm("mov.b64 %0, {%1,%2};" : "=l"(dxy) : "f"(v.x), "f"(v.y));
    asm("mov.b64 %0, {%1,%2};" : "=l"(dzw) : "f"(v.z), "f"(v.w));
    asm("add.rn.f32x2 %0, %1, %2;" : "=l"(b1xy) : "l"(dxy), "l"(MAGIC2));
    asm("add.rn.f32x2 %0, %1, %2;" : "=l"(b1zw) : "l"(dzw), "l"(MAGIC2));
    asm("fma.rn.f32x2 %0, %1, %2, %3;" : "=l"(t) : "l"(dxy), "l"(INV12_2), "l"(BIAS2));
    asm("add.rn.f32x2 %0, %1, %2;" : "=l"(b2xy) : "l"(t), "l"(MAGIC2));
    asm("fma.rn.f32x2 %0, %1, %2, %3;" : "=l"(t) : "l"(dzw), "l"(INV12_2), "l"(BIAS2));
    asm("add.rn.f32x2 %0, %1, %2;" : "=l"(b2zw) : "l"(t), "l"(MAGIC2));
    unsigned a0, a1, a2, a3, q0, q1, q2, q3;
    asm("mov.b64 {%0,%1}, %2;" : "=r"(a0), "=r"(a1) : "l"(b1xy));
    asm("mov.b64 {%0,%1}, %2;" : "=r"(a2), "=r"(a3) : "l"(b1zw));
    asm("mov.b64 {%0,%1}, %2;" : "=r"(q0), "=r"(q1) : "l"(b2xy));
    asm("mov.b64 {%0,%1}, %2;" : "=r"(q2), "=r"(q3) : "l"(b2zw));
    return (1u << ((a0 - 12u * q0) & 31u))
         | (1u << ((a1 - 12u * q1) & 31u))
         | (1u << ((a2 - 12u * q2) & 31u))
         | (1u << ((a3 - 12u * q3) & 31u));
}

__device__ __forceinline__ void doChunk(
    unsigned pm, unsigned tm, int r, int T, bool own,
    const unsigned* __restrict__ sT60, const uint2* __restrict__ sSim,
    unsigned long long& simAcc, unsigned& penAcc)
{
    int p  = __popc(pm);                      // 1..4
    int q  = __popc(tm);
    int it = __popc(pm & tm);

    uint2 ra = sSim[p * 4 + q];
    if (own && (r < T)) simAcc += (unsigned long long)((unsigned)it * ra.x + ra.y);

    unsigned Tp = sT60[p];
    unsigned iM0 = __popc(pm & 0x091u), iM1 = __popc(pm & 0x221u), iM2 = __popc(pm & 0x884u);
    unsigned im0 = __popc(pm & 0x089u), im1 = __popc(pm & 0x121u), im2 = __popc(pm & 0x484u);
    unsigned selP = iM0 | (im0 << 4) | (iM2 << 8) | (im2 << 12);
    unsigned selQ = iM1 | (im1 << 4);
    unsigned P = __byte_perm(Tp, 0, selP);    // {tM0, tm0, tM2, tm2}
    unsigned Q = __byte_perm(Tp, 0, selQ);    // {tM1, tm1, -, -}

    unsigned Q1 = __shfl_down_sync(0xffffffffu, Q, 1);
    unsigned P2 = __shfl_down_sync(0xffffffffu, P, 2);
    unsigned P3 = __shfl_down_sync(0xffffffffu, P, 3);

    unsigned v1 = __byte_perm(P,  Q1, 0x0040);
    unsigned v2 = __byte_perm(P2, P3, 0x0042);
    unsigned majW = __byte_perm(v1, v2, 0x5410);
    unsigned w1 = __byte_perm(P,  Q1, 0x0051);
    unsigned w2 = __byte_perm(P2, P3, 0x0053);
    unsigned minW = __byte_perm(w1, w2, 0x5410);

    unsigned SM = __dp4a(majW, 0x01010101u, 0u);
    unsigned Sm = __dp4a(minW, 0x01010101u, 0u);
    if (own && (r <= T - 4)) penAcc += (SM > Sm) ? SM : Sm;   // 240*(1-min)
}

__global__ __launch_bounds__(THREADS, 2) void chord_fused(
    const float4* __restrict__ pred, const float4* __restrict__ targ,
    float* __restrict__ out, int T, int nUnits)
{
    __shared__ unsigned sT60[5];
    __shared__ uint2    sSim[21];
    __shared__ unsigned long long redS[WPB], redP[WPB];
    __shared__ bool     sLast;

    const int tid = threadIdx.x;
    if (tid < 5) {
        int p = tid; unsigned w = 0;
        for (int i = 0; i < 4; i++) {
            int dnm = p + 3 - i;
            unsigned t = (dnm > 0) ? (unsigned)((60 * i) / dnm) : 0u;
            w |= (t & 0xFFu) << (8 * i);
        }
        sT60[p] = w;
    }
    if (tid < 16) {
        int p = (tid >> 2) + 1, q = (tid & 3) + 1;
        double r = 1.0 / (((double)p + 12e-6) * ((double)q + 12e-6));
        unsigned R30 = (unsigned)__double2ll_rn(r * 1073741824.0);
        unsigned A30 = (unsigned)__double2ll_rn((1e-6 * (p + q) + 1.2e-11) * r * 1073741824.0);
        sSim[p * 4 + q] = make_uint2(R30, A30);
    }
    __syncthreads();

    const int lane = tid & 31;
    const int wid  = tid >> 5;
    const bool laneOwn = (lane < 29);

    unsigned long long simAcc = 0ull;
    unsigned penAcc = 0u;
    const int rMax = (T > 0) ? (T - 1) : 0;

    // each warp: exactly UPW consecutive units, pipelined
    const int uBase = (blockIdx.x * WPB + wid) * UPW;
    int rA = uBase * 58 + lane;
    int rB = rA + 29;

    int cA = (rA < rMax) ? rA : rMax;
    int cB = (rB < rMax) ? rB : rMax;
    float4 pA = pred[cA], tA = targ[cA];
    float4 pB = pred[cB], tB = targ[cB];

    #pragma unroll
    for (int k = 0; k < UPW; k++) {
        // convert current (float4s die here)
        unsigned pmA = pcmask(pA), tmA = pcmask(tA);
        unsigned pmB = pcmask(pB), tmB = pcmask(tB);

        const int rAc = rA, rBc = rB;

        // prefetch next unit (overwrites float4 regs; masks already extracted)
        if (k + 1 < UPW) {
            rA += 58; rB += 58;
            cA = (rA < rMax) ? rA : rMax;
            cB = (rB < rMax) ? rB : rMax;
            pA = pred[cA]; tA = targ[cA];
            pB = pred[cB]; tB = targ[cB];
        }

        const bool vOwn = laneOwn && (uBase + k < nUnits);
        doChunk(pmA, tmA, rAc, T, vOwn, sT60, sSim, simAcc, penAcc);
        doChunk(pmB, tmB, rBc, T, vOwn, sT60, sSim, simAcc, penAcc);
    }

    // warp reduction (exact integers -> order-independent)
    unsigned long long penW = (unsigned long long)penAcc;
    #pragma unroll
    for (int o = 16; o; o >>= 1) {
        simAcc += __shfl_xor_sync(0xffffffffu, simAcc, o);
        penW   += __shfl_xor_sync(0xffffffffu, penW,   o);
    }
    if (lane == 0) { redS[wid] = simAcc; redP[wid] = penW; }
    __syncthreads();

    if (wid == 0) {
        unsigned long long s = (lane < WPB) ? redS[lane] : 0ull;
        unsigned long long p = (lane < WPB) ? redP[lane] : 0ull;
        #pragma unroll
        for (int o = 16; o; o >>= 1) {
            s += __shfl_xor_sync(0xffffffffu, s, o);
            p += __shfl_xor_sync(0xffffffffu, p, o);
        }
        if (lane == 0) {
            int slot = blockIdx.x & 31;
            atomicAdd(&g_simSlots[slot], s);
            atomicAdd(&g_penSlots[slot], p);
            __threadfence();
            sLast = (atomicAdd(&g_count, 1u) == gridDim.x - 1);
        }
    }
    __syncthreads();

    if (sLast && wid == 0) {
        __threadfence();
        unsigned long long s = *(volatile unsigned long long*)&g_simSlots[lane];
        unsigned long long p = *(volatile unsigned long long*)&g_penSlots[lane];
        #pragma unroll
        for (int o = 16; o; o >>= 1) {
            s += __shfl_xor_sync(0xffffffffu, s, o);
            p += __shfl_xor_sync(0xffffffffu, p, o);
        }
        if (lane == 0) {
            double simMean = ((double)s * (1.0 / 1073741824.0)) / (double)T;
            long long nWin = (long long)T - 3;
            double pen = (nWin > 0) ? (0.5 - (double)p / (480.0 * (double)nWin)) : 0.0;
            out[0] = (float)((1.0 - simMean) + pen);
        }
        g_simSlots[lane] = 0ull;   // self-reset for graph replay
        g_penSlots[lane] = 0ull;
        if (lane == 0) g_count = 0;
    }
}

extern "C" void kernel_launch(void* const* d_in, const int* in_sizes, int n_in,
                              void* d_out, int out_size)
{
    const float4* pred = (const float4*)d_in[0];
    const float4* targ = (const float4*)d_in[1];
    int T1 = in_sizes[0] / 4;
    int T2 = in_sizes[1] / 4;
    int T = (T1 < T2) ? T1 : T2;

    int nUnits = (T + 57) / 58;
    if (nUnits < 1) nUnits = 1;
    int nWarps = (nUnits + UPW - 1) / UPW;
    int blocks = (nWarps + WPB - 1) / WPB;

    chord_fused<<<blocks, THREADS>>>(pred, targ, (float*)d_out, T, nUnits);
}